// round 8
// baseline (speedup 1.0000x reference)
#include <cuda_runtime.h>
#include <cuda_bf16.h>

// Shapes fixed by the problem definition.
#define BATCH    256
#define HWPIX    1024           // 32*32
#define CHAN     256
#define NPART    4
#define PSIZE    64             // BATCH / NPART
#define EPSV     0.001f
#define NUNITS   4096u          // BATCH * 16 chunks of 64 pixels
#define UNIT_PIX 64
#define CPS      6              // CTAs per SM (residency floor)

// Scratch (allocation-free rule): device globals. All counters/accumulators
// are returned to zero by in-kernel handshakes before the kernel retires ->
// every graph replay sees identical initial state (deterministic).
__device__ float    g_sum[NPART][CHAN];
__device__ float    g_sq [NPART][CHAN];
__device__ unsigned g_tk1;    // phase-1 ticket   (reset by barrier master)
__device__ unsigned g_tk2;    // phase-2 ticket   (reset by last finisher)
__device__ unsigned g_cnt1;   // barrier arrivals (reset by barrier master)
__device__ unsigned g_rel1;   // barrier release epoch (monotonic)
__device__ unsigned g_fc;     // fold-consumed counter (reset by its last)
__device__ unsigned g_done;   // phase-2 finishers (reset by last finisher)

// ---------------------------------------------------------------------------
// One persistent kernel: stats -> grid barrier -> fold -> normalize.
// grid = CPS * num_SMs with __launch_bounds__(256,CPS) => all CTAs resident
// (software grid barrier deadlock-free) AND regs capped at 42 so occupancy
// reaches 48 warps/SM (R7 ran 64 regs -> 32 warps -> DRAM starved at 75%).
// Both phases pull 64-pixel units from a global atomic ticket (perfect
// balance, R7-validated). Phase 2 consumes tickets in REVERSE global order
// to hit the L2-resident x tail from phase 1 (~60 MB saved, R5-validated).
// ---------------------------------------------------------------------------
__global__ void __launch_bounds__(256, CPS)
k_fused(const float4* __restrict__ x, float4* __restrict__ out,
        const float* __restrict__ gamma, const float* __restrict__ beta,
        const int* __restrict__ perm) {
    const int      t    = threadIdx.x;
    const int      c4   = t & 63;
    const int      psub = t >> 6;
    const unsigned nCTA = gridDim.x;

    __shared__ int      spart[BATCH];    // partition of each batch index
    __shared__ float    ssum[4][CHAN];
    __shared__ float    ssq [4][CHAN];
    __shared__ float    sscale[NPART][CHAN];
    __shared__ float    sbias [NPART][CHAN];
    __shared__ unsigned stk[2];          // double-buffered ticket broadcast
    __shared__ int      slast;

    // Build partition map per-CTA: position of b in perm, / 64.
    spart[perm[t]] = t >> 6;             // t / PSIZE
    // (published by the first __syncthreads in the loop below)

    // ---------------- Phase 1: stats (dynamic tickets, forward) ----------
    for (unsigned it = 0; ; it++) {
        if (t == 0) stk[it & 1u] = atomicAdd(&g_tk1, 1u);
        __syncthreads();                 // publish ticket (and spart on it=0)
        const unsigned u = stk[it & 1u];
        if (u >= NUNITS) break;

        const int b     = (int)(u >> 4);
        const int chunk = (int)(u & 15);
        const float4* base =
            x + ((size_t)b * HWPIX + (size_t)chunk * UNIT_PIX) * (CHAN / 4) + c4;

        float4 s = make_float4(0.f, 0.f, 0.f, 0.f);
        float4 q = make_float4(0.f, 0.f, 0.f, 0.f);
        #pragma unroll
        for (int i = 0; i < 16; i++) {
            float4 v = base[(size_t)(i * 4 + psub) * (CHAN / 4)];
            s.x += v.x; s.y += v.y; s.z += v.z; s.w += v.w;
            q.x += v.x * v.x; q.y += v.y * v.y; q.z += v.z * v.z; q.w += v.w * v.w;
        }

        const int cbase = c4 * 4;
        ssum[psub][cbase + 0] = s.x; ssum[psub][cbase + 1] = s.y;
        ssum[psub][cbase + 2] = s.z; ssum[psub][cbase + 3] = s.w;
        ssq[psub][cbase + 0]  = q.x; ssq[psub][cbase + 1]  = q.y;
        ssq[psub][cbase + 2]  = q.z; ssq[psub][cbase + 3]  = q.w;
        __syncthreads();

        const int p = spart[b];
        atomicAdd(&g_sum[p][t], ssum[0][t] + ssum[1][t] + ssum[2][t] + ssum[3][t]);
        atomicAdd(&g_sq[p][t],  ssq[0][t]  + ssq[1][t]  + ssq[2][t]  + ssq[3][t]);
        // (ssum reads are ordered before the next iteration's writes by the
        //  ticket-publish __syncthreads at the top of the loop)
    }

    // ---------------- Grid barrier (all atomics visible) -----------------
    __syncthreads();
    if (t == 0) {
        __threadfence();
        unsigned r0  = atomicAdd(&g_rel1, 0u);        // epoch before arriving
        unsigned old = atomicAdd(&g_cnt1, 1u);
        if (old == nCTA - 1u) {                       // master: everyone done
            atomicExch(&g_cnt1, 0u);                  // reset for next replay
            atomicExch(&g_tk1, 0u);                   // no more phase-1 grabs
            __threadfence();
            atomicAdd(&g_rel1, 1u);                   // release
        } else {
            while (atomicAdd(&g_rel1, 0u) == r0) { __nanosleep(64); }
        }
        __threadfence();
    }
    __syncthreads();

    // -------- Fold stats into fused scale/bias in shared (once/CTA) ------
    {
        const float invN = 1.0f / (float)(PSIZE * HWPIX);
        const float* sm = &g_sum[0][0];
        const float* sq = &g_sq[0][0];
        float* sc = &sscale[0][0];
        float* sb = &sbias[0][0];
        #pragma unroll
        for (int i = t; i < NPART * CHAN; i += 256) {
            float mean = sm[i] * invN;
            float var  = sq[i] * invN - mean * mean;
            float s    = gamma[i] * rsqrtf(var + EPSV);
            sc[i] = s;
            sb[i] = beta[i] - mean * s;
        }
        __syncthreads();
        // Last CTA to consume the accumulators re-zeroes them.
        if (t == 0) slast = (atomicAdd(&g_fc, 1u) == nCTA - 1u) ? 1 : 0;
        __syncthreads();
        if (slast) {
            float* gs = &g_sum[0][0];
            float* gq = &g_sq[0][0];
            #pragma unroll
            for (int i = t; i < NPART * CHAN; i += 256) { gs[i] = 0.f; gq[i] = 0.f; }
            __threadfence();
            if (t == 0) atomicExch(&g_fc, 0u);
        }
    }

    // ---------------- Phase 2: normalize (dynamic tickets, REVERSED) -----
    for (unsigned it = 0; ; it++) {
        if (t == 0) stk[it & 1u] = atomicAdd(&g_tk2, 1u);
        __syncthreads();
        const unsigned tk = stk[it & 1u];
        if (tk >= NUNITS) break;
        const unsigned u = NUNITS - 1u - tk;          // newest-read units first

        const int b     = (int)(u >> 4);
        const int chunk = (int)(u & 15);
        const int p     = spart[b];

        const float4 sc = *(const float4*)&sscale[p][c4 * 4];
        const float4 bi = *(const float4*)&sbias[p][c4 * 4];

        const size_t base =
            ((size_t)b * HWPIX + (size_t)chunk * UNIT_PIX) * (CHAN / 4) + c4;
        #pragma unroll
        for (int i = 0; i < 16; i++) {
            size_t idx = base + (size_t)(i * 4 + psub) * (CHAN / 4);
            float4 v = x[idx];
            v.x = v.x * sc.x + bi.x;
            v.y = v.y * sc.y + bi.y;
            v.z = v.z * sc.z + bi.z;
            v.w = v.w * sc.w + bi.w;
            out[idx] = v;
        }
    }

    // ---------------- Exit handshake: reset tickets for next replay ------
    __syncthreads();
    if (t == 0) slast = (atomicAdd(&g_done, 1u) == nCTA - 1u) ? 1 : 0;
    __syncthreads();
    if (slast && t == 0) {
        atomicExch(&g_tk2, 0u);
        __threadfence();
        atomicExch(&g_done, 0u);
    }
}

// ---------------------------------------------------------------------------
extern "C" void kernel_launch(void* const* d_in, const int* in_sizes, int n_in,
                              void* d_out, int out_size) {
    const float* x     = (const float*)d_in[0];
    const float* gamma = (const float*)d_in[1];
    const float* beta  = (const float*)d_in[2];
    const int*   perm  = (const int*)d_in[3];

    int nsm = 0;
    cudaDeviceGetAttribute(&nsm, cudaDevAttrMultiProcessorCount, 0);
    if (nsm <= 0) nsm = 148;                 // defensive fallback
    const int grid = CPS * nsm;              // __launch_bounds__(256,CPS) => resident

    k_fused<<<grid, 256>>>((const float4*)x, (float4*)d_out, gamma, beta, perm);
}

// round 9
// speedup vs baseline: 1.0126x; 1.0126x over previous
#include <cuda_runtime.h>
#include <cuda_bf16.h>

// Shapes fixed by the problem definition.
#define BATCH    256
#define HWPIX    1024           // 32*32
#define CHAN     256
#define NPART    4
#define PSIZE    64             // BATCH / NPART
#define EPSV     0.001f
#define NUNITS   4096u          // phase-1: 64-pixel CTA units
#define UNIT_PIX 64
#define NUNITS2  16384u         // phase-2: 16-pixel WARP units
#define UNIT2_PIX 16
#define CPS      4              // CTAs per SM (R7-proven: 64 regs, high MLP)

// Scratch (allocation-free rule): device globals. All counters/accumulators
// are returned to zero by in-kernel handshakes before the kernel retires ->
// every graph replay sees identical initial state (deterministic).
__device__ float    g_sum[NPART][CHAN];
__device__ float    g_sq [NPART][CHAN];
__device__ unsigned g_tk1;    // phase-1 ticket   (reset by barrier master)
__device__ unsigned g_tk2;    // phase-2 ticket   (reset by last finisher)
__device__ unsigned g_cnt1;   // barrier arrivals (reset by barrier master)
__device__ unsigned g_rel1;   // barrier release epoch (monotonic)
__device__ unsigned g_fc;     // fold-consumed counter (reset by its last)
__device__ unsigned g_done;   // phase-2 finishers (reset by last finisher)

// ---------------------------------------------------------------------------
// One persistent kernel: stats -> grid barrier -> fold -> normalize.
// grid = CPS*num_SMs, __launch_bounds__(256,CPS) => all CTAs resident, so the
// software grid barrier is deadlock-free. Phase 1: CTA-level dynamic tickets
// (R7-validated). Phase 2: WARP-level dynamic tickets with NO __syncthreads
// -- each warp streams independently, keeping the memory pipe full across
// unit boundaries (R7's per-unit block sync drained MLP every 256 KB).
// Phase 2 consumes tickets in REVERSE order for the L2-resident x tail.
// ---------------------------------------------------------------------------
__global__ void __launch_bounds__(256, CPS)
k_fused(const float4* __restrict__ x, float4* __restrict__ out,
        const float* __restrict__ gamma, const float* __restrict__ beta,
        const int* __restrict__ perm) {
    const int      t    = threadIdx.x;
    const int      c4   = t & 63;
    const int      psub = t >> 6;
    const int      lane = t & 31;
    const unsigned nCTA = gridDim.x;

    __shared__ int      spart[BATCH];    // partition of each batch index
    __shared__ float    ssum[4][CHAN];
    __shared__ float    ssq [4][CHAN];
    __shared__ float    sscale[NPART][CHAN];
    __shared__ float    sbias [NPART][CHAN];
    __shared__ unsigned stk[2];          // double-buffered ticket broadcast
    __shared__ int      slast;

    // Build partition map per-CTA: position of b in perm, / 64.
    spart[perm[t]] = t >> 6;             // t / PSIZE
    // (published by the first __syncthreads in the loop below)

    // ---------------- Phase 1: stats (CTA tickets, forward) --------------
    for (unsigned it = 0; ; it++) {
        if (t == 0) stk[it & 1u] = atomicAdd(&g_tk1, 1u);
        __syncthreads();                 // publish ticket (and spart on it=0)
        const unsigned u = stk[it & 1u];
        if (u >= NUNITS) break;

        const int b     = (int)(u >> 4);
        const int chunk = (int)(u & 15);
        const float4* base =
            x + ((size_t)b * HWPIX + (size_t)chunk * UNIT_PIX) * (CHAN / 4) + c4;

        float4 s = make_float4(0.f, 0.f, 0.f, 0.f);
        float4 q = make_float4(0.f, 0.f, 0.f, 0.f);
        #pragma unroll
        for (int i = 0; i < 16; i++) {
            float4 v = base[(size_t)(i * 4 + psub) * (CHAN / 4)];
            s.x += v.x; s.y += v.y; s.z += v.z; s.w += v.w;
            q.x += v.x * v.x; q.y += v.y * v.y; q.z += v.z * v.z; q.w += v.w * v.w;
        }

        const int cbase = c4 * 4;
        ssum[psub][cbase + 0] = s.x; ssum[psub][cbase + 1] = s.y;
        ssum[psub][cbase + 2] = s.z; ssum[psub][cbase + 3] = s.w;
        ssq[psub][cbase + 0]  = q.x; ssq[psub][cbase + 1]  = q.y;
        ssq[psub][cbase + 2]  = q.z; ssq[psub][cbase + 3]  = q.w;
        __syncthreads();

        const int p = spart[b];
        atomicAdd(&g_sum[p][t], ssum[0][t] + ssum[1][t] + ssum[2][t] + ssum[3][t]);
        atomicAdd(&g_sq[p][t],  ssq[0][t]  + ssq[1][t]  + ssq[2][t]  + ssq[3][t]);
    }

    // ---------------- Grid barrier (all atomics visible) -----------------
    __syncthreads();
    if (t == 0) {
        __threadfence();
        unsigned r0  = atomicAdd(&g_rel1, 0u);        // epoch before arriving
        unsigned old = atomicAdd(&g_cnt1, 1u);
        if (old == nCTA - 1u) {                       // master: everyone done
            atomicExch(&g_cnt1, 0u);                  // reset for next replay
            atomicExch(&g_tk1, 0u);
            __threadfence();
            atomicAdd(&g_rel1, 1u);                   // release
        } else {
            while (atomicAdd(&g_rel1, 0u) == r0) { __nanosleep(64); }
        }
        __threadfence();
    }
    __syncthreads();

    // -------- Fold stats into fused scale/bias in shared (once/CTA) ------
    {
        const float invN = 1.0f / (float)(PSIZE * HWPIX);
        const float* sm = &g_sum[0][0];
        const float* sq = &g_sq[0][0];
        float* sc = &sscale[0][0];
        float* sb = &sbias[0][0];
        #pragma unroll
        for (int i = t; i < NPART * CHAN; i += 256) {
            float mean = sm[i] * invN;
            float var  = sq[i] * invN - mean * mean;
            float s    = gamma[i] * rsqrtf(var + EPSV);
            sc[i] = s;
            sb[i] = beta[i] - mean * s;
        }
        __syncthreads();
        // Last CTA to consume the accumulators re-zeroes them.
        if (t == 0) slast = (atomicAdd(&g_fc, 1u) == nCTA - 1u) ? 1 : 0;
        __syncthreads();
        if (slast) {
            float* gs = &g_sum[0][0];
            float* gq = &g_sq[0][0];
            #pragma unroll
            for (int i = t; i < NPART * CHAN; i += 256) { gs[i] = 0.f; gq[i] = 0.f; }
            __threadfence();
            if (t == 0) atomicExch(&g_fc, 0u);
        }
    }

    // -------- Phase 2: normalize (WARP tickets, REVERSED, sync-free) -----
    // Lane l owns channel quads l and l+32 (channels 4l..4l+3, 128+4l..).
    // Warp unit = 16 pixel rows. Consecutive lanes -> consecutive float4:
    // two perfectly coalesced 512B segments per access.
    for (;;) {
        unsigned tk;
        if (lane == 0) tk = atomicAdd(&g_tk2, 1u);
        tk = __shfl_sync(0xffffffffu, tk, 0);
        if (tk >= NUNITS2) break;
        const unsigned u = NUNITS2 - 1u - tk;         // newest-read units first

        const int b    = (int)(u >> 6);               // 64 units per batch
        const int pix0 = (int)(u & 63) * UNIT2_PIX;
        const int p    = spart[b];

        const float4 sc0 = *(const float4*)&sscale[p][lane * 4];
        const float4 bi0 = *(const float4*)&sbias [p][lane * 4];
        const float4 sc1 = *(const float4*)&sscale[p][128 + lane * 4];
        const float4 bi1 = *(const float4*)&sbias [p][128 + lane * 4];

        const size_t base = ((size_t)b * HWPIX + (size_t)pix0) * (CHAN / 4);
        #pragma unroll
        for (int i = 0; i < UNIT2_PIX; i++) {
            const size_t row = base + (size_t)i * (CHAN / 4);
            float4 v0 = x[row + lane];
            float4 v1 = x[row + 32 + lane];
            v0.x = v0.x * sc0.x + bi0.x;
            v0.y = v0.y * sc0.y + bi0.y;
            v0.z = v0.z * sc0.z + bi0.z;
            v0.w = v0.w * sc0.w + bi0.w;
            v1.x = v1.x * sc1.x + bi1.x;
            v1.y = v1.y * sc1.y + bi1.y;
            v1.z = v1.z * sc1.z + bi1.z;
            v1.w = v1.w * sc1.w + bi1.w;
            out[row + lane]      = v0;
            out[row + 32 + lane] = v1;
        }
    }

    // ---------------- Exit handshake: reset tickets for next replay ------
    __syncthreads();                     // all warps of this CTA done
    if (t == 0) slast = (atomicAdd(&g_done, 1u) == nCTA - 1u) ? 1 : 0;
    __syncthreads();
    if (slast && t == 0) {
        atomicExch(&g_tk2, 0u);
        __threadfence();
        atomicExch(&g_done, 0u);
    }
}

// ---------------------------------------------------------------------------
extern "C" void kernel_launch(void* const* d_in, const int* in_sizes, int n_in,
                              void* d_out, int out_size) {
    const float* x     = (const float*)d_in[0];
    const float* gamma = (const float*)d_in[1];
    const float* beta  = (const float*)d_in[2];
    const int*   perm  = (const int*)d_in[3];

    int nsm = 0;
    cudaDeviceGetAttribute(&nsm, cudaDevAttrMultiProcessorCount, 0);
    if (nsm <= 0) nsm = 148;                 // defensive fallback
    const int grid = CPS * nsm;              // __launch_bounds__ => all resident

    k_fused<<<grid, 256>>>((const float4*)x, (float4*)d_out, gamma, beta, perm);
}

// round 10
// speedup vs baseline: 1.0408x; 1.0279x over previous
#include <cuda_runtime.h>
#include <cuda_bf16.h>

// Shapes fixed by the problem definition.
#define BATCH    256
#define HWPIX    1024           // 32*32
#define CHAN     256
#define NPART    4
#define PSIZE    64             // BATCH / NPART
#define EPSV     0.001f
#define NUNITS   4096u          // 64-pixel CTA units (both phases)
#define UNIT_PIX 64
#define CPS      4              // CTAs per SM (R7-proven: 64 regs, high MLP)

// Scratch (allocation-free rule): device globals. All counters/accumulators
// are returned to zero by in-kernel handshakes before the kernel retires ->
// every graph replay sees identical initial state (deterministic).
__device__ float    g_sum[NPART][CHAN];
__device__ float    g_sq [NPART][CHAN];
__device__ unsigned g_tk1;    // phase-1 ticket   (reset by barrier master)
__device__ unsigned g_tk2;    // phase-2 ticket   (reset by last finisher)
__device__ unsigned g_cnt1;   // barrier arrivals (reset by barrier master)
__device__ unsigned g_rel1;   // barrier release epoch (monotonic)
__device__ unsigned g_fc;     // fold-consumed counter (reset by its last)
__device__ unsigned g_done;   // phase-2 finishers (reset by last finisher)

// ---------------------------------------------------------------------------
// One persistent kernel: stats -> grid barrier -> fold -> normalize.
// R7 skeleton with PIPELINED tickets: the next unit's ticket atomic is issued
// BEFORE the current unit's work, so its ~318-cycle L2 latency hides under
// the unit's 16 KB of loads, and only ONE __syncthreads per unit remains
// (publishes the next ticket + fences smem). Phase-1's reduction arrays are
// double-buffered so the next unit's smem writes can't race this unit's
// reduction reads (removes the second per-unit sync R7 had).
// ---------------------------------------------------------------------------
__global__ void __launch_bounds__(256, CPS)
k_fused(const float4* __restrict__ x, float4* __restrict__ out,
        const float* __restrict__ gamma, const float* __restrict__ beta,
        const int* __restrict__ perm) {
    const int      t    = threadIdx.x;
    const int      c4   = t & 63;
    const int      psub = t >> 6;
    const unsigned nCTA = gridDim.x;

    __shared__ int      spart[BATCH];      // partition of each batch index
    __shared__ float    ssum[2][4][CHAN];  // double-buffered reduction arrays
    __shared__ float    ssq [2][4][CHAN];
    __shared__ float    sscale[NPART][CHAN];
    __shared__ float    sbias [NPART][CHAN];
    __shared__ unsigned stk[2];            // double-buffered ticket broadcast
    __shared__ int      slast;

    // Build partition map per-CTA: position of b in perm, / 64.
    spart[perm[t]] = t >> 6;               // t / PSIZE

    // ---------------- Phase 1: stats (pipelined CTA tickets) -------------
    if (t == 0) stk[0] = atomicAdd(&g_tk1, 1u);
    __syncthreads();                       // publish first ticket + spart
    for (unsigned it = 0; ; it++) {
        const unsigned u = stk[it & 1u];
        if (u >= NUNITS) break;
        if (t == 0) stk[(it + 1u) & 1u] = atomicAdd(&g_tk1, 1u);  // prefetch

        const int b     = (int)(u >> 4);
        const int chunk = (int)(u & 15);
        const float4* base =
            x + ((size_t)b * HWPIX + (size_t)chunk * UNIT_PIX) * (CHAN / 4) + c4;

        float4 s = make_float4(0.f, 0.f, 0.f, 0.f);
        float4 q = make_float4(0.f, 0.f, 0.f, 0.f);
        #pragma unroll
        for (int i = 0; i < 16; i++) {
            float4 v = base[(size_t)(i * 4 + psub) * (CHAN / 4)];
            s.x += v.x; s.y += v.y; s.z += v.z; s.w += v.w;
            q.x += v.x * v.x; q.y += v.y * v.y; q.z += v.z * v.z; q.w += v.w * v.w;
        }

        float (*su)[CHAN] = ssum[it & 1u];
        float (*sv)[CHAN] = ssq [it & 1u];
        const int cbase = c4 * 4;
        su[psub][cbase + 0] = s.x; su[psub][cbase + 1] = s.y;
        su[psub][cbase + 2] = s.z; su[psub][cbase + 3] = s.w;
        sv[psub][cbase + 0] = q.x; sv[psub][cbase + 1] = q.y;
        sv[psub][cbase + 2] = q.z; sv[psub][cbase + 3] = q.w;
        __syncthreads();     // single sync: next ticket visible + smem fenced

        const int p = spart[b];
        atomicAdd(&g_sum[p][t], su[0][t] + su[1][t] + su[2][t] + su[3][t]);
        atomicAdd(&g_sq[p][t],  sv[0][t] + sv[1][t] + sv[2][t] + sv[3][t]);
        // next iteration writes the OTHER buffer -> these reads are safe
    }

    // ---------------- Grid barrier (all atomics visible) -----------------
    __syncthreads();
    if (t == 0) {
        __threadfence();
        unsigned r0  = atomicAdd(&g_rel1, 0u);        // epoch before arriving
        unsigned old = atomicAdd(&g_cnt1, 1u);
        if (old == nCTA - 1u) {                       // master: everyone done
            atomicExch(&g_cnt1, 0u);                  // reset for next replay
            atomicExch(&g_tk1, 0u);
            __threadfence();
            atomicAdd(&g_rel1, 1u);                   // release
        } else {
            while (atomicAdd(&g_rel1, 0u) == r0) { __nanosleep(64); }
        }
        __threadfence();
    }
    __syncthreads();

    // -------- Fold stats into fused scale/bias in shared (once/CTA) ------
    {
        const float invN = 1.0f / (float)(PSIZE * HWPIX);
        const float* sm = &g_sum[0][0];
        const float* sq = &g_sq[0][0];
        float* sc = &sscale[0][0];
        float* sb = &sbias[0][0];
        #pragma unroll
        for (int i = t; i < NPART * CHAN; i += 256) {
            float mean = sm[i] * invN;
            float var  = sq[i] * invN - mean * mean;
            float s    = gamma[i] * rsqrtf(var + EPSV);
            sc[i] = s;
            sb[i] = beta[i] - mean * s;
        }
        __syncthreads();
        // Last CTA to consume the accumulators re-zeroes them.
        if (t == 0) slast = (atomicAdd(&g_fc, 1u) == nCTA - 1u) ? 1 : 0;
        __syncthreads();
        if (slast) {
            float* gs = &g_sum[0][0];
            float* gq = &g_sq[0][0];
            #pragma unroll
            for (int i = t; i < NPART * CHAN; i += 256) { gs[i] = 0.f; gq[i] = 0.f; }
            __threadfence();
            if (t == 0) atomicExch(&g_fc, 0u);
        }
    }

    // ------- Phase 2: normalize (pipelined CTA tickets, REVERSED) --------
    if (t == 0) stk[0] = atomicAdd(&g_tk2, 1u);
    __syncthreads();
    for (unsigned it = 0; ; it++) {
        const unsigned tk = stk[it & 1u];
        if (tk >= NUNITS) break;
        if (t == 0) stk[(it + 1u) & 1u] = atomicAdd(&g_tk2, 1u);  // prefetch
        const unsigned u = NUNITS - 1u - tk;          // newest-read units first

        const int b     = (int)(u >> 4);
        const int chunk = (int)(u & 15);
        const int p     = spart[b];

        const float4 sc = *(const float4*)&sscale[p][c4 * 4];
        const float4 bi = *(const float4*)&sbias[p][c4 * 4];

        const size_t base =
            ((size_t)b * HWPIX + (size_t)chunk * UNIT_PIX) * (CHAN / 4) + c4;
        #pragma unroll
        for (int i = 0; i < 16; i++) {
            size_t idx = base + (size_t)(i * 4 + psub) * (CHAN / 4);
            float4 v = x[idx];
            v.x = v.x * sc.x + bi.x;
            v.y = v.y * sc.y + bi.y;
            v.z = v.z * sc.z + bi.z;
            v.w = v.w * sc.w + bi.w;
            out[idx] = v;
        }
        __syncthreads();     // single sync: publish the prefetched ticket
    }

    // ---------------- Exit handshake: reset tickets for next replay ------
    __syncthreads();
    if (t == 0) slast = (atomicAdd(&g_done, 1u) == nCTA - 1u) ? 1 : 0;
    __syncthreads();
    if (slast && t == 0) {
        atomicExch(&g_tk2, 0u);
        __threadfence();
        atomicExch(&g_done, 0u);
    }
}

// ---------------------------------------------------------------------------
extern "C" void kernel_launch(void* const* d_in, const int* in_sizes, int n_in,
                              void* d_out, int out_size) {
    const float* x     = (const float*)d_in[0];
    const float* gamma = (const float*)d_in[1];
    const float* beta  = (const float*)d_in[2];
    const int*   perm  = (const int*)d_in[3];

    int nsm = 0;
    cudaDeviceGetAttribute(&nsm, cudaDevAttrMultiProcessorCount, 0);
    if (nsm <= 0) nsm = 148;                 // defensive fallback
    const int grid = CPS * nsm;              // __launch_bounds__ => all resident

    k_fused<<<grid, 256>>>((const float4*)x, (float4*)d_out, gamma, beta, perm);
}